// round 1
// baseline (speedup 1.0000x reference)
#include <cuda_runtime.h>
#include <math.h>

#define B_ 8
#define N_ 2048
#define C_ 1024
#define H_ 16
#define D_ 64
#define R_ 5
#define RM_ 10

#define BM 128
#define BN 128
#define BK 16
#define NKT (C_/BK)
#define CP 129          // padded row stride for epilogue C tile (conflict-free column reads)

#define ATTN_ELEMS ((size_t)B_*N_*C_)              // 16777216
#define ESC_ELEMS  ((size_t)B_*H_*N_*R_)           // 1310720

// scratch (static device globals: no allocation)
__device__ float g_we[B_*H_*D_*R_];
__device__ float g_wr[B_*H_*D_*R_];
__device__ float g_S[H_*R_*R_*R_];

__constant__ int c_idx[RM_] = {0,227,454,682,909,1137,1364,1592,1819,2047};

typedef unsigned long long ull;

__device__ __forceinline__ void ffma2(ull &d, ull a, ull b){
    asm("fma.rn.f32x2 %0, %1, %2, %0;" : "+l"(d) : "l"(a), "l"(b));
}
__device__ __forceinline__ ull pack2(float lo, float hi){
    ull r; asm("mov.b64 %0, {%1, %2};" : "=l"(r) : "f"(lo), "f"(hi)); return r;
}

// ---------------------------------------------------------------------------
// Setup kernel 1: we/wr inducing-point projections.
// we[b,h,d,a] = sum_m x[b, idx[m], h*64+d] * we_p[h,m,a]
// ---------------------------------------------------------------------------
__global__ void k_setup_wewr(const float* __restrict__ x,
                             const float* __restrict__ we_p,
                             const float* __restrict__ wr_p)
{
    int blk = blockIdx.x;
    int b = blk >> 4, h = blk & 15;
    int d = threadIdx.x;
    if (d >= D_) return;
    float xs[RM_];
#pragma unroll
    for (int m = 0; m < RM_; m++)
        xs[m] = x[((size_t)(b*N_ + c_idx[m]))*C_ + h*D_ + d];
#pragma unroll
    for (int a = 0; a < R_; a++){
        float se = 0.f, sr = 0.f;
#pragma unroll
        for (int m = 0; m < RM_; m++){
            se += xs[m] * we_p[(h*RM_ + m)*R_ + a];
            sr += xs[m] * wr_p[(h*RM_ + m)*R_ + a];
        }
        g_we[((b*H_ + h)*D_ + d)*R_ + a] = se;
        g_wr[((b*H_ + h)*D_ + d)*R_ + a] = sr;
    }
}

// ---------------------------------------------------------------------------
// Setup kernel 2: build S matrices and the KL scalar.
// S[h,a,u,c] = exp(log_ssqrt[h,a,u]) if u==c ; s_tri[h,a,u,c] if u>c ; else 0
// ---------------------------------------------------------------------------
__global__ void k_setup_skl(const float* __restrict__ log_lam,
                            const float* __restrict__ m_u,
                            const float* __restrict__ s_tri,
                            const float* __restrict__ log_ssqrt,
                            float* __restrict__ kl_out)
{
    int t = threadIdx.x;
    for (int i = t; i < H_*R_*R_*R_; i += blockDim.x){
        int c = i % R_;
        int u = (i / R_) % R_;
        int a = (i / (R_*R_)) % R_;
        int h = i / (R_*R_*R_);
        float v = 0.f;
        if (u == c)      v = expf(log_ssqrt[(h*R_ + a)*R_ + u]);
        else if (u > c)  v = s_tri[((h*R_ + a)*R_ + u)*R_ + c];
        g_S[i] = v;
    }
    __shared__ float part[128];
    float p = 0.f;
    if (t < H_*R_){
        int h = t / R_, a = t % R_;
        float ll = log_lam[t];
        float e4 = expf(4.f*ll);
        float ss2 = 0.f;
        for (int u = 0; u < R_; u++){
            float dg = expf(log_ssqrt[(h*R_ + a)*R_ + u]);
            ss2 += dg*dg;
            for (int c = 0; c < u; c++){
                float v = s_tri[((h*R_ + a)*R_ + u)*R_ + c];
                ss2 += v*v;
            }
        }
        float mm = 0.f;
        for (int s = 0; s < R_; s++){
            float v = m_u[(h*R_ + a)*R_ + s];
            mm += v*v;
        }
        float lsum = 0.f;
        for (int u = 0; u < R_; u++) lsum += log_ssqrt[(h*R_ + a)*R_ + u];
        // 0.5*e4*(S^2 sum) + 0.5*e4*(mu^2 sum) - sum(ls) - 2*r*ll - (0.5*r*r*H)/(H*r)
        p = 0.5f*e4*(ss2 + mm) - lsum - 2.f*(float)R_*ll
            - (0.5f*(float)(R_*R_*H_)) / (float)(H_*R_);
    }
    part[t] = p;
    __syncthreads();
    if (t == 0){
        float s = 0.f;
        for (int i = 0; i < H_*R_; i++) s += part[i];
        *kl_out = s;
    }
}

// ---------------------------------------------------------------------------
// Fused main kernel: per block, a 128(rows n) x 128(cols: q-dims 0..63, k-dims
// 64..127 of head h) fp32 GEMM over K=1024 with fma.rn.f32x2 inner loop,
// then full in-block epilogue (l2norm, escore/rscore, v1, mean+noise, fw proj).
// ---------------------------------------------------------------------------
extern __shared__ float smem_dyn[];

__device__ __forceinline__ void store_tile(float* __restrict__ Ab, float* __restrict__ Bb,
                                           int m, int qh,
                                           const float4& ra0, const float4& ra1,
                                           const float4& rb0, const float4& rb1)
{
    int k0 = qh*4;
    Ab[(k0+0)*BM + m] = ra0.x; Ab[(k0+1)*BM + m] = ra0.y;
    Ab[(k0+2)*BM + m] = ra0.z; Ab[(k0+3)*BM + m] = ra0.w;
    Ab[(k0+8)*BM + m] = ra1.x; Ab[(k0+9)*BM + m] = ra1.y;
    Ab[(k0+10)*BM + m] = ra1.z; Ab[(k0+11)*BM + m] = ra1.w;
    Bb[(k0+0)*BN + m] = rb0.x; Bb[(k0+1)*BN + m] = rb0.y;
    Bb[(k0+2)*BN + m] = rb0.z; Bb[(k0+3)*BN + m] = rb0.w;
    Bb[(k0+8)*BN + m] = rb1.x; Bb[(k0+9)*BN + m] = rb1.y;
    Bb[(k0+10)*BN + m] = rb1.z; Bb[(k0+11)*BN + m] = rb1.w;
}

__global__ __launch_bounds__(256, 2)
void k_main(const float* __restrict__ x,
            const float* __restrict__ mask,
            const float* __restrict__ eps,
            const float* __restrict__ qk_w,
            const float* __restrict__ log_lam,
            const float* __restrict__ m_u,
            const float* __restrict__ fw_w,
            const float* __restrict__ fw_b,
            float* __restrict__ out)
{
    const int nb = blockIdx.x, h = blockIdx.y, b = blockIdx.z;
    const int tid = threadIdx.x;

    float* As = smem_dyn;                    // [2][BK][BM]
    float* Bs = smem_dyn + 2*BK*BM;          // [2][BK][BN]
    float* Ct = smem_dyn;                    // [BM][CP]  (reuses GEMM buffers)

    __shared__ float we_s[D_*R_], wr_s[D_*R_], fww_s[D_*R_];
    __shared__ float S_s[R_*R_*R_], mu_s[R_*R_], lam2_s[R_], fwb_s[D_];

    // load small per-(b,h) operands (consumed after mainloop syncs)
    {
        int base = (b*H_ + h)*D_*R_;
        for (int i = tid; i < D_*R_; i += 256){
            we_s[i] = g_we[base + i];
            wr_s[i] = g_wr[base + i];
            fww_s[i] = fw_w[i];
        }
        for (int i = tid; i < R_*R_*R_; i += 256) S_s[i] = g_S[h*R_*R_*R_ + i];
        for (int i = tid; i < R_*R_; i += 256)    mu_s[i] = m_u[h*R_*R_ + i];
        if (tid < R_)  lam2_s[tid] = expf(2.f*log_lam[h*R_ + tid]);
        if (tid < D_)  fwb_s[tid] = fw_b[tid];
    }

    // ---- GEMM ----
    const int m  = tid & 127;                 // row (for A) / col (for B) within tile
    const int qh = tid >> 7;                  // 0/1 -> k-chunk pair {qh, qh+2}
    const float* xrow = x + ((size_t)(b*N_ + nb*BM + m))*C_;
    const int wj = (m < 64) ? (h*64 + m) : (C_ + h*64 + (m - 64));
    const float* wrow = qk_w + (size_t)wj*C_;

    const int tx = tid & 15, ty = tid >> 4;

    ull acc[4][8];
#pragma unroll
    for (int i = 0; i < 4; i++)
#pragma unroll
        for (int j = 0; j < 8; j++) acc[i][j] = 0ull;

    float4 ra0, ra1, rb0, rb1;
    // prologue: tile 0
    ra0 = *(const float4*)(xrow + qh*4);
    ra1 = *(const float4*)(xrow + qh*4 + 8);
    rb0 = *(const float4*)(wrow + qh*4);
    rb1 = *(const float4*)(wrow + qh*4 + 8);
    store_tile(As, Bs, m, qh, ra0, ra1, rb0, rb1);
    __syncthreads();

    for (int kt = 0; kt < NKT; ++kt){
        const int cur = kt & 1;
        if (kt + 1 < NKT){
            const float* xp = xrow + (kt+1)*BK;
            const float* wp = wrow + (kt+1)*BK;
            ra0 = *(const float4*)(xp + qh*4);
            ra1 = *(const float4*)(xp + qh*4 + 8);
            rb0 = *(const float4*)(wp + qh*4);
            rb1 = *(const float4*)(wp + qh*4 + 8);
        }
        const float* Ab = As + cur*BK*BM;
        const float* Bb = Bs + cur*BK*BN;
#pragma unroll
        for (int kk = 0; kk < BK; kk++){
            ulonglong2 a01 = *(const ulonglong2*)(Ab + kk*BM + ty*8);
            ulonglong2 a23 = *(const ulonglong2*)(Ab + kk*BM + ty*8 + 4);
            float4 b0 = *(const float4*)(Bb + kk*BN + tx*8);
            float4 b1 = *(const float4*)(Bb + kk*BN + tx*8 + 4);
            ull aa[4] = {a01.x, a01.y, a23.x, a23.y};
            ull bb[8] = {pack2(b0.x,b0.x), pack2(b0.y,b0.y), pack2(b0.z,b0.z), pack2(b0.w,b0.w),
                         pack2(b1.x,b1.x), pack2(b1.y,b1.y), pack2(b1.z,b1.z), pack2(b1.w,b1.w)};
#pragma unroll
            for (int i = 0; i < 4; i++)
#pragma unroll
                for (int j = 0; j < 8; j++)
                    ffma2(acc[i][j], aa[i], bb[j]);
        }
        if (kt + 1 < NKT)
            store_tile(As + (cur^1)*BK*BM, Bs + (cur^1)*BK*BN, m, qh, ra0, ra1, rb0, rb1);
        __syncthreads();
    }

    // ---- write tile to smem for row-wise epilogue ----
#pragma unroll
    for (int i = 0; i < 4; i++)
#pragma unroll
        for (int j = 0; j < 8; j++){
            float2 v = *reinterpret_cast<float2*>(&acc[i][j]);
            Ct[(ty*8 + 2*i    )*CP + tx*8 + j] = v.x;
            Ct[(ty*8 + 2*i + 1)*CP + tx*8 + j] = v.y;
        }
    __syncthreads();

    // ---- epilogue: one thread per row n ----
    if (tid < BM){
        const int n = nb*BM + tid;
        const float* row = Ct + tid*CP;
        const float mval = mask[b*N_ + n];

        // q: sumsq + raw scores in one pass
        float e[R_] = {0,0,0,0,0};
        float sq = 0.f;
        for (int d = 0; d < D_; d++){
            float qd = row[d];
            sq += qd*qd;
#pragma unroll
            for (int a = 0; a < R_; a++) e[a] += qd * we_s[d*R_ + a];
        }
        float sclq = mval / fmaxf(fabsf(mval)*sqrtf(sq), 1e-12f);

        float rr[R_] = {0,0,0,0,0};
        float sk = 0.f;
        for (int d = 0; d < D_; d++){
            float kd = row[D_ + d];
            sk += kd*kd;
#pragma unroll
            for (int a = 0; a < R_; a++) rr[a] += kd * wr_s[d*R_ + a];
        }
        float sclk = mval / fmaxf(fabsf(mval)*sqrtf(sk), 1e-12f);

        const size_t ebase = ((size_t)((b*H_ + h)*N_ + n))*R_;
        float es[R_], rs[R_], v1[R_];
#pragma unroll
        for (int a = 0; a < R_; a++){
            es[a] = e[a]*sclq;
            rs[a] = rr[a]*sclk;
            v1[a] = (es[a] + rs[a]) * lam2_s[a];
        }
        // escore / rscore outputs
        float* eo = out + ATTN_ELEMS + ebase;
        float* ro = out + ATTN_ELEMS + ESC_ELEMS + ebase;
#pragma unroll
        for (int a = 0; a < R_; a++){ eo[a] = es[a]; ro[a] = rs[a]; }

        // samples = mean + noise
        float ev[R_];
#pragma unroll
        for (int u = 0; u < R_; u++) ev[u] = eps[ebase + u];
        float smp[R_];
#pragma unroll
        for (int s = 0; s < R_; s++){
            float acc_m = 0.f;
#pragma unroll
            for (int a = 0; a < R_; a++) acc_m += v1[a]*mu_s[a*R_ + s];
            smp[s] = acc_m;
        }
#pragma unroll
        for (int a = 0; a < R_; a++)
#pragma unroll
            for (int u = 0; u < R_; u++){
                float f = v1[a]*ev[u];
#pragma unroll
                for (int c = 0; c < R_; c++)
                    smp[c] += f * S_s[(a*R_ + u)*R_ + c];
            }

        // attn_out = samples @ fw_w^T + fw_b  (64 dims, float4 stores)
        float* ob = out + ((size_t)(b*N_ + n))*C_ + h*D_;
        for (int d0 = 0; d0 < D_; d0 += 4){
            float4 o;
            float* op = (float*)&o;
#pragma unroll
            for (int dd = 0; dd < 4; dd++){
                float acc_o = fwb_s[d0 + dd];
#pragma unroll
                for (int a = 0; a < R_; a++) acc_o += smp[a]*fww_s[(d0 + dd)*R_ + a];
                op[dd] = acc_o;
            }
            *(float4*)(ob + d0) = o;
        }
    }
}

// ---------------------------------------------------------------------------
extern "C" void kernel_launch(void* const* d_in, const int* in_sizes, int n_in,
                              void* d_out, int out_size)
{
    const float* x         = (const float*)d_in[0];
    const float* mask      = (const float*)d_in[1];
    const float* eps       = (const float*)d_in[2];
    const float* qk_w      = (const float*)d_in[3];
    const float* we_p      = (const float*)d_in[4];
    const float* wr_p      = (const float*)d_in[5];
    const float* log_lam   = (const float*)d_in[6];
    const float* m_u       = (const float*)d_in[7];
    const float* s_tri     = (const float*)d_in[8];
    const float* log_ssqrt = (const float*)d_in[9];
    const float* fw_w      = (const float*)d_in[10];
    const float* fw_b      = (const float*)d_in[11];
    float* out = (float*)d_out;

    k_setup_wewr<<<B_*H_, 64>>>(x, we_p, wr_p);
    k_setup_skl<<<1, 128>>>(log_lam, m_u, s_tri, log_ssqrt,
                            out + ATTN_ELEMS + 2*ESC_ELEMS);

    const int smem = BM*CP*(int)sizeof(float);   // 66048 B (>= GEMM's 32KB)
    cudaFuncSetAttribute(k_main, cudaFuncAttributeMaxDynamicSharedMemorySize, smem);
    dim3 grid(N_/BM, H_, B_);
    k_main<<<grid, 256, smem>>>(x, mask, eps, qk_w, log_lam, m_u, fw_w, fw_b, out);
}

// round 3
// speedup vs baseline: 2.1827x; 2.1827x over previous
#include <cuda_runtime.h>
#include <cuda_bf16.h>
#include <math.h>
#include <stdint.h>

#define B_ 8
#define N_ 2048
#define C_ 1024
#define H_ 16
#define D_ 64
#define R_ 5
#define RM_ 10

#define ATTN_ELEMS ((size_t)B_*N_*C_)              // 16777216
#define ESC_ELEMS  ((size_t)B_*H_*N_*R_)           // 1310720

// GEMM tiling
#define BM 128
#define BN 128
#define BK 32                 // K elems per stage
#define NSTAGE (C_/BK)        // 32
#define ROWP 40               // padded smem row stride in bf16 elems (80B)
#define TERM_BYTES (128*ROWP*2)          // one 128-row tile, 10240 B
#define STAGE_BYTES (4*TERM_BYTES)       // Ahi Alo Bhi Blo = 40960 B
#define SMEM_DYN (2*STAGE_BYTES)         // 81920 (>= 128*129*4=66048 C tile)
#define CP 129

// ---------------- static device scratch (no allocation) ----------------
__device__ __align__(256) __nv_bfloat16 g_xhi[B_*N_*C_];
__device__ __align__(256) __nv_bfloat16 g_xlo[B_*N_*C_];
__device__ __align__(256) __nv_bfloat16 g_whi[2*C_*C_];
__device__ __align__(256) __nv_bfloat16 g_wlo[2*C_*C_];
__device__ float g_we[B_*H_*D_*R_];
__device__ float g_wr[B_*H_*D_*R_];
__device__ float g_S[H_*R_*R_*R_];

__constant__ int c_idx[RM_] = {0,227,454,682,909,1137,1364,1592,1819,2047};

// ---------------- PTX helpers (all baseline / portable) ----------------
__device__ __forceinline__ uint32_t smem_u32(const void* p){
    uint32_t a;
    asm("{ .reg .u64 t; cvta.to.shared.u64 t, %1; cvt.u32.u64 %0, t; }" : "=r"(a) : "l"(p));
    return a;
}
__device__ __forceinline__ void ldgsts16(uint32_t dst, const void* src){
    asm volatile("cp.async.cg.shared.global [%0], [%1], 16;" :: "r"(dst), "l"(src));
}
__device__ __forceinline__ void cp_commit(){ asm volatile("cp.async.commit_group;" ::: "memory"); }
__device__ __forceinline__ void cp_wait1(){ asm volatile("cp.async.wait_group 1;" ::: "memory"); }
__device__ __forceinline__ void cp_wait0(){ asm volatile("cp.async.wait_group 0;" ::: "memory"); }

__device__ __forceinline__ void ldm_x4(uint32_t* r, uint32_t addr){
    asm volatile("ldmatrix.sync.aligned.m8n8.x4.shared.b16 {%0,%1,%2,%3}, [%4];"
        : "=r"(r[0]),"=r"(r[1]),"=r"(r[2]),"=r"(r[3]) : "r"(addr));
}
__device__ __forceinline__ void mma_bf16(float* d, const uint32_t* a, uint32_t b0, uint32_t b1){
    asm volatile("mma.sync.aligned.m16n8k16.row.col.f32.bf16.bf16.f32 "
        "{%0,%1,%2,%3}, {%4,%5,%6,%7}, {%8,%9}, {%0,%1,%2,%3};"
        : "+f"(d[0]),"+f"(d[1]),"+f"(d[2]),"+f"(d[3])
        : "r"(a[0]),"r"(a[1]),"r"(a[2]),"r"(a[3]), "r"(b0),"r"(b1));
}

// ---------------------------------------------------------------------------
// Convert fp32 -> bf16 hi/lo split for x and qk_w
// ---------------------------------------------------------------------------
__global__ void k_convert(const float* __restrict__ x, const float* __restrict__ qk_w)
{
    const size_t nx4 = (size_t)B_*N_*C_/4;
    const size_t nw4 = (size_t)2*C_*C_/4;
    const size_t tot = nx4 + nw4;
    size_t stride = (size_t)gridDim.x*blockDim.x;
    for (size_t t = (size_t)blockIdx.x*blockDim.x + threadIdx.x; t < tot; t += stride){
        float4 v = (t < nx4) ? ((const float4*)x)[t] : ((const float4*)qk_w)[t - nx4];
        __nv_bfloat16 h0 = __float2bfloat16_rn(v.x);
        __nv_bfloat16 h1 = __float2bfloat16_rn(v.y);
        __nv_bfloat16 h2 = __float2bfloat16_rn(v.z);
        __nv_bfloat16 h3 = __float2bfloat16_rn(v.w);
        __nv_bfloat16 l0 = __float2bfloat16_rn(v.x - __bfloat162float(h0));
        __nv_bfloat16 l1 = __float2bfloat16_rn(v.y - __bfloat162float(h1));
        __nv_bfloat16 l2 = __float2bfloat16_rn(v.z - __bfloat162float(h2));
        __nv_bfloat16 l3 = __float2bfloat16_rn(v.w - __bfloat162float(h3));
        uint2 hp, lp;
        hp.x = ((uint32_t)__bfloat16_as_ushort(h1) << 16) | __bfloat16_as_ushort(h0);
        hp.y = ((uint32_t)__bfloat16_as_ushort(h3) << 16) | __bfloat16_as_ushort(h2);
        lp.x = ((uint32_t)__bfloat16_as_ushort(l1) << 16) | __bfloat16_as_ushort(l0);
        lp.y = ((uint32_t)__bfloat16_as_ushort(l3) << 16) | __bfloat16_as_ushort(l2);
        if (t < nx4){
            ((uint2*)g_xhi)[t] = hp; ((uint2*)g_xlo)[t] = lp;
        } else {
            ((uint2*)g_whi)[t - nx4] = hp; ((uint2*)g_wlo)[t - nx4] = lp;
        }
    }
}

// ---------------------------------------------------------------------------
// we/wr inducing-point projections (fp32, tiny)
// ---------------------------------------------------------------------------
__global__ void k_setup_wewr(const float* __restrict__ x,
                             const float* __restrict__ we_p,
                             const float* __restrict__ wr_p)
{
    int blk = blockIdx.x;
    int b = blk >> 4, h = blk & 15;
    int d = threadIdx.x;
    if (d >= D_) return;
    float xs[RM_];
#pragma unroll
    for (int m = 0; m < RM_; m++)
        xs[m] = x[((size_t)(b*N_ + c_idx[m]))*C_ + h*D_ + d];
#pragma unroll
    for (int a = 0; a < R_; a++){
        float se = 0.f, sr = 0.f;
#pragma unroll
        for (int m = 0; m < RM_; m++){
            se += xs[m] * we_p[(h*RM_ + m)*R_ + a];
            sr += xs[m] * wr_p[(h*RM_ + m)*R_ + a];
        }
        g_we[((b*H_ + h)*D_ + d)*R_ + a] = se;
        g_wr[((b*H_ + h)*D_ + d)*R_ + a] = sr;
    }
}

// ---------------------------------------------------------------------------
// S matrices + KL scalar
// ---------------------------------------------------------------------------
__global__ void k_setup_skl(const float* __restrict__ log_lam,
                            const float* __restrict__ m_u,
                            const float* __restrict__ s_tri,
                            const float* __restrict__ log_ssqrt,
                            float* __restrict__ kl_out)
{
    int t = threadIdx.x;
    for (int i = t; i < H_*R_*R_*R_; i += blockDim.x){
        int c = i % R_;
        int u = (i / R_) % R_;
        int a = (i / (R_*R_)) % R_;
        int h = i / (R_*R_*R_);
        float v = 0.f;
        if (u == c)      v = expf(log_ssqrt[(h*R_ + a)*R_ + u]);
        else if (u > c)  v = s_tri[((h*R_ + a)*R_ + u)*R_ + c];
        g_S[i] = v;
    }
    __shared__ float part[128];
    float p = 0.f;
    if (t < H_*R_){
        int h = t / R_, a = t % R_;
        float ll = log_lam[t];
        float e4 = expf(4.f*ll);
        float ss2 = 0.f;
        for (int u = 0; u < R_; u++){
            float dg = expf(log_ssqrt[(h*R_ + a)*R_ + u]);
            ss2 += dg*dg;
            for (int c = 0; c < u; c++){
                float v = s_tri[((h*R_ + a)*R_ + u)*R_ + c];
                ss2 += v*v;
            }
        }
        float mm = 0.f;
        for (int s = 0; s < R_; s++){
            float v = m_u[(h*R_ + a)*R_ + s];
            mm += v*v;
        }
        float lsum = 0.f;
        for (int u = 0; u < R_; u++) lsum += log_ssqrt[(h*R_ + a)*R_ + u];
        p = 0.5f*e4*(ss2 + mm) - lsum - 2.f*(float)R_*ll
            - (0.5f*(float)(R_*R_*H_)) / (float)(H_*R_);
    }
    part[t] = p;
    __syncthreads();
    if (t == 0){
        float s = 0.f;
        for (int i = 0; i < H_*R_; i++) s += part[i];
        *kl_out = s;
    }
}

// ---------------------------------------------------------------------------
// Fused main kernel: 128x128x1024 bf16-split mma.sync GEMM per CTA + epilogue
// ---------------------------------------------------------------------------
extern __shared__ char smem_raw[];

__global__ __launch_bounds__(256, 1)
void k_main(const float* __restrict__ mask,
            const float* __restrict__ eps,
            const float* __restrict__ log_lam,
            const float* __restrict__ m_u,
            const float* __restrict__ fw_w,
            const float* __restrict__ fw_b,
            float* __restrict__ out)
{
    const int nb = blockIdx.x, h = blockIdx.y, b = blockIdx.z;
    const int tid = threadIdx.x;
    const int wid = tid >> 5;
    const int lane = tid & 31;
    const uint32_t sb = smem_u32(smem_raw);

    __shared__ float we_s[D_*R_], wr_s[D_*R_], fww_s[D_*R_];
    __shared__ float S_s[R_*R_*R_], mu_s[R_*R_], lam2_s[R_], fwb_s[D_];

    {
        int base = (b*H_ + h)*D_*R_;
        for (int i = tid; i < D_*R_; i += 256){
            we_s[i] = g_we[base + i];
            wr_s[i] = g_wr[base + i];
            fww_s[i] = fw_w[i];
        }
        for (int i = tid; i < R_*R_*R_; i += 256) S_s[i] = g_S[h*R_*R_*R_ + i];
        for (int i = tid; i < R_*R_; i += 256)    mu_s[i] = m_u[h*R_*R_ + i];
        if (tid < R_)  lam2_s[tid] = expf(2.f*log_lam[h*R_ + tid]);
        if (tid < D_)  fwb_s[tid] = fw_b[tid];
    }

    const int rowA0 = b*N_ + nb*BM;

    // ---- cp.async load geometry: 8 chunks of 16B per thread per stage ----
    // chunk c = i*256 + tid: half=c/1024 (A/B), term=(c%1024)/512 (hi/lo),
    // row=(c%512)/4, quad=c%4
    const __nv_bfloat16* gsrc[8];
    uint32_t soff[8];
#pragma unroll
    for (int i = 0; i < 8; i++){
        int c = i*256 + tid;
        int half = c >> 10;
        int term = (c >> 9) & 1;
        int row  = (c >> 2) & 127;
        int quad = c & 3;
        soff[i] = half*2*TERM_BYTES + term*TERM_BYTES + row*(ROWP*2) + quad*16;
        if (half == 0){
            const __nv_bfloat16* g = term ? g_xlo : g_xhi;
            gsrc[i] = g + ((size_t)(rowA0 + row))*C_ + quad*8;
        } else {
            int wj = (row < 64) ? (h*64 + row) : (C_ + h*64 + (row - 64));
            const __nv_bfloat16* g = term ? g_wlo : g_whi;
            gsrc[i] = g + (size_t)wj*C_ + quad*8;
        }
    }

    auto load_stage = [&](int kt, int buf){
        uint32_t stb = sb + buf*STAGE_BYTES;
#pragma unroll
        for (int i = 0; i < 8; i++)
            ldgsts16(stb + soff[i], gsrc[i] + kt*BK);
        cp_commit();
    };

    // ---- warp tile geometry ----
    const int wm = wid >> 2;        // 0/1 : m offset 64*wm
    const int wn = wid & 3;         // 0-3 : n offset 32*wn
    const int arow = lane & 15, acol8 = lane >> 4;   // ldmatrix x4 source lanes

    // per-lane smem ldmatrix byte offsets (within a term tile)
    // A tile i (0..3), k16 kk (0..1): (wm*64 + i*16 + arow)*80 + (kk*16 + acol8*8)*2
    // B pair p (0..1),  k16 kk:       (wn*32 + p*16 + arow)*80 + (kk*16 + acol8*8)*2
    uint32_t aoff[4][2], boff[2][2];
#pragma unroll
    for (int i = 0; i < 4; i++)
#pragma unroll
        for (int kk = 0; kk < 2; kk++)
            aoff[i][kk] = (wm*64 + i*16 + arow)*(ROWP*2) + (kk*16 + acol8*8)*2;
#pragma unroll
    for (int p = 0; p < 2; p++)
#pragma unroll
        for (int kk = 0; kk < 2; kk++)
            boff[p][kk] = (wn*32 + p*16 + arow)*(ROWP*2) + (kk*16 + acol8*8)*2;

    float acc[16][4];
#pragma unroll
    for (int i = 0; i < 16; i++)
#pragma unroll
        for (int j = 0; j < 4; j++) acc[i][j] = 0.f;

    // ---- pipeline ----
    load_stage(0, 0);
    __syncthreads();   // also covers the shared-operand preload above

    for (int kt = 0; kt < NSTAGE; kt++){
        const int cur = kt & 1;
        if (kt + 1 < NSTAGE){
            load_stage(kt + 1, cur ^ 1);
            cp_wait1();
        } else {
            cp_wait0();
        }
        __syncthreads();

        const uint32_t Ah = sb + cur*STAGE_BYTES;
        const uint32_t Al = Ah + TERM_BYTES;
        const uint32_t Bh = Ah + 2*TERM_BYTES;
        const uint32_t Bl = Ah + 3*TERM_BYTES;

#pragma unroll
        for (int kk = 0; kk < 2; kk++){
            uint32_t ah[4][4], al[4][4], bh[2][4], bl[2][4];
#pragma unroll
            for (int i = 0; i < 4; i++){
                ldm_x4(ah[i], Ah + aoff[i][kk]);
                ldm_x4(al[i], Al + aoff[i][kk]);
            }
#pragma unroll
            for (int p = 0; p < 2; p++){
                ldm_x4(bh[p], Bh + boff[p][kk]);
                ldm_x4(bl[p], Bl + boff[p][kk]);
            }
#pragma unroll
            for (int i = 0; i < 4; i++)
#pragma unroll
                for (int j = 0; j < 4; j++){
                    int p = j >> 1, s = j & 1;
                    mma_bf16(acc[i*4+j], ah[i], bh[p][s], bh[p][2+s]);
                    mma_bf16(acc[i*4+j], al[i], bh[p][s], bh[p][2+s]);
                    mma_bf16(acc[i*4+j], ah[i], bl[p][s], bl[p][2+s]);
                }
        }
        __syncthreads();   // protect buffer cur^1 refill next iter / C-tile reuse
    }

    // ---- write C tile to smem (reuse stage buffers) ----
    float* Ct = (float*)smem_raw;
    {
        const int r0 = wm*64 + (lane >> 2);
        const int c0 = wn*32 + (lane & 3)*2;
#pragma unroll
        for (int i = 0; i < 4; i++)
#pragma unroll
            for (int j = 0; j < 4; j++){
                int rr = r0 + i*16, cc = c0 + j*8;
                Ct[rr*CP + cc]       = acc[i*4+j][0];
                Ct[rr*CP + cc + 1]   = acc[i*4+j][1];
                Ct[(rr+8)*CP + cc]   = acc[i*4+j][2];
                Ct[(rr+8)*CP + cc+1] = acc[i*4+j][3];
            }
    }
    __syncthreads();

    // ---- epilogue: one thread per row n ----
    if (tid < BM){
        const int n = nb*BM + tid;
        const float* row = Ct + tid*CP;
        const float mval = mask[b*N_ + n];

        float e[R_] = {0,0,0,0,0};
        float sq = 0.f;
        for (int d = 0; d < D_; d++){
            float qd = row[d];
            sq += qd*qd;
#pragma unroll
            for (int a = 0; a < R_; a++) e[a] += qd * we_s[d*R_ + a];
        }
        float sclq = mval / fmaxf(fabsf(mval)*sqrtf(sq), 1e-12f);

        float rr[R_] = {0,0,0,0,0};
        float sk = 0.f;
        for (int d = 0; d < D_; d++){
            float kd = row[D_ + d];
            sk += kd*kd;
#pragma unroll
            for (int a = 0; a < R_; a++) rr[a] += kd * wr_s[d*R_ + a];
        }
        float sclk = mval / fmaxf(fabsf(mval)*sqrtf(sk), 1e-12f);

        const size_t ebase = ((size_t)((b*H_ + h)*N_ + n))*R_;
        float es[R_], rs[R_], v1[R_];
#pragma unroll
        for (int a = 0; a < R_; a++){
            es[a] = e[a]*sclq;
            rs[a] = rr[a]*sclk;
            v1[a] = (es[a] + rs[a]) * lam2_s[a];
        }
        float* eo = out + ATTN_ELEMS + ebase;
        float* ro = out + ATTN_ELEMS + ESC_ELEMS + ebase;
#pragma unroll
        for (int a = 0; a < R_; a++){ eo[a] = es[a]; ro[a] = rs[a]; }

        float ev[R_];
#pragma unroll
        for (int u = 0; u < R_; u++) ev[u] = eps[ebase + u];
        float smp[R_];
#pragma unroll
        for (int s = 0; s < R_; s++){
            float am = 0.f;
#pragma unroll
            for (int a = 0; a < R_; a++) am += v1[a]*mu_s[a*R_ + s];
            smp[s] = am;
        }
#pragma unroll
        for (int a = 0; a < R_; a++)
#pragma unroll
            for (int u = 0; u < R_; u++){
                float f = v1[a]*ev[u];
#pragma unroll
                for (int c = 0; c < R_; c++)
                    smp[c] += f * S_s[(a*R_ + u)*R_ + c];
            }

        float* ob = out + ((size_t)(b*N_ + n))*C_ + h*D_;
#pragma unroll
        for (int d0 = 0; d0 < D_; d0 += 4){
            float4 o;
            float* op = (float*)&o;
#pragma unroll
            for (int dd = 0; dd < 4; dd++){
                float ao = fwb_s[d0 + dd];
#pragma unroll
                for (int a = 0; a < R_; a++) ao += smp[a]*fww_s[(d0 + dd)*R_ + a];
                op[dd] = ao;
            }
            *(float4*)(ob + d0) = o;
        }
    }
}

// ---------------------------------------------------------------------------
extern "C" void kernel_launch(void* const* d_in, const int* in_sizes, int n_in,
                              void* d_out, int out_size)
{
    const float* x         = (const float*)d_in[0];
    const float* mask      = (const float*)d_in[1];
    const float* eps       = (const float*)d_in[2];
    const float* qk_w      = (const float*)d_in[3];
    const float* we_p      = (const float*)d_in[4];
    const float* wr_p      = (const float*)d_in[5];
    const float* log_lam   = (const float*)d_in[6];
    const float* m_u       = (const float*)d_in[7];
    const float* s_tri     = (const float*)d_in[8];
    const float* log_ssqrt = (const float*)d_in[9];
    const float* fw_w      = (const float*)d_in[10];
    const float* fw_b      = (const float*)d_in[11];
    float* out = (float*)d_out;

    k_convert<<<4096, 256>>>(x, qk_w);
    k_setup_wewr<<<B_*H_, 64>>>(x, we_p, wr_p);
    k_setup_skl<<<1, 128>>>(log_lam, m_u, s_tri, log_ssqrt,
                            out + ATTN_ELEMS + 2*ESC_ELEMS);

    cudaFuncSetAttribute(k_main, cudaFuncAttributeMaxDynamicSharedMemorySize, SMEM_DYN);
    dim3 grid(N_/BM, H_, B_);
    k_main<<<grid, 256, SMEM_DYN>>>(mask, eps, log_lam, m_u, fw_w, fw_b, out);
}

// round 4
// speedup vs baseline: 2.2697x; 1.0399x over previous
#include <cuda_runtime.h>
#include <cuda_bf16.h>
#include <math.h>
#include <stdint.h>

#define B_ 8
#define N_ 2048
#define C_ 1024
#define H_ 16
#define D_ 64
#define R_ 5
#define RM_ 10

#define ATTN_ELEMS ((size_t)B_*N_*C_)              // 16777216
#define ESC_ELEMS  ((size_t)B_*H_*N_*R_)           // 1310720

// GEMM tiling
#define BM 128
#define BN 128
#define BK 32                 // K elems per stage
#define NSTAGE (C_/BK)        // 32
#define ROWP 40               // padded smem row stride in bf16 elems (80B)
#define TERM_BYTES (128*ROWP*2)          // one 128-row tile, 10240 B
#define STAGE_BYTES (4*TERM_BYTES)       // Ahi Alo Bhi Blo = 40960 B
#define NBUF 4
#define SMEM_DYN (NBUF*STAGE_BYTES)      // 163840
#define CP 129

// ---------------- static device scratch (no allocation) ----------------
__device__ __align__(256) __nv_bfloat16 g_xhi[B_*N_*C_];
__device__ __align__(256) __nv_bfloat16 g_xlo[B_*N_*C_];
__device__ __align__(256) __nv_bfloat16 g_whi[2*C_*C_];
__device__ __align__(256) __nv_bfloat16 g_wlo[2*C_*C_];
__device__ float g_we[B_*H_*D_*R_];
__device__ float g_wr[B_*H_*D_*R_];
__device__ float g_S[H_*R_*R_*R_];

__constant__ int c_idx[RM_] = {0,227,454,682,909,1137,1364,1592,1819,2047};

// ---------------- PTX helpers (all baseline / portable) ----------------
__device__ __forceinline__ uint32_t smem_u32(const void* p){
    uint32_t a;
    asm("{ .reg .u64 t; cvta.to.shared.u64 t, %1; cvt.u32.u64 %0, t; }" : "=r"(a) : "l"(p));
    return a;
}
__device__ __forceinline__ void ldgsts16(uint32_t dst, const void* src){
    asm volatile("cp.async.cg.shared.global [%0], [%1], 16;" :: "r"(dst), "l"(src));
}
__device__ __forceinline__ void cp_commit(){ asm volatile("cp.async.commit_group;" ::: "memory"); }
__device__ __forceinline__ void cp_wait2(){ asm volatile("cp.async.wait_group 2;" ::: "memory"); }
__device__ __forceinline__ void cp_wait1(){ asm volatile("cp.async.wait_group 1;" ::: "memory"); }
__device__ __forceinline__ void cp_wait0(){ asm volatile("cp.async.wait_group 0;" ::: "memory"); }

__device__ __forceinline__ void ldm_x4(uint32_t* r, uint32_t addr){
    asm volatile("ldmatrix.sync.aligned.m8n8.x4.shared.b16 {%0,%1,%2,%3}, [%4];"
        : "=r"(r[0]),"=r"(r[1]),"=r"(r[2]),"=r"(r[3]) : "r"(addr));
}
__device__ __forceinline__ void mma_bf16(float* d, const uint32_t* a, uint32_t b0, uint32_t b1){
    asm volatile("mma.sync.aligned.m16n8k16.row.col.f32.bf16.bf16.f32 "
        "{%0,%1,%2,%3}, {%4,%5,%6,%7}, {%8,%9}, {%0,%1,%2,%3};"
        : "+f"(d[0]),"+f"(d[1]),"+f"(d[2]),"+f"(d[3])
        : "r"(a[0]),"r"(a[1]),"r"(a[2]),"r"(a[3]), "r"(b0),"r"(b1));
}

// ---------------------------------------------------------------------------
// Convert fp32 -> bf16 hi/lo split for x and qk_w
// ---------------------------------------------------------------------------
__global__ void k_convert(const float* __restrict__ x, const float* __restrict__ qk_w)
{
    const size_t nx4 = (size_t)B_*N_*C_/4;
    const size_t nw4 = (size_t)2*C_*C_/4;
    const size_t tot = nx4 + nw4;
    size_t stride = (size_t)gridDim.x*blockDim.x;
    for (size_t t = (size_t)blockIdx.x*blockDim.x + threadIdx.x; t < tot; t += stride){
        float4 v = (t < nx4) ? ((const float4*)x)[t] : ((const float4*)qk_w)[t - nx4];
        __nv_bfloat16 h0 = __float2bfloat16_rn(v.x);
        __nv_bfloat16 h1 = __float2bfloat16_rn(v.y);
        __nv_bfloat16 h2 = __float2bfloat16_rn(v.z);
        __nv_bfloat16 h3 = __float2bfloat16_rn(v.w);
        __nv_bfloat16 l0 = __float2bfloat16_rn(v.x - __bfloat162float(h0));
        __nv_bfloat16 l1 = __float2bfloat16_rn(v.y - __bfloat162float(h1));
        __nv_bfloat16 l2 = __float2bfloat16_rn(v.z - __bfloat162float(h2));
        __nv_bfloat16 l3 = __float2bfloat16_rn(v.w - __bfloat162float(h3));
        uint2 hp, lp;
        hp.x = ((uint32_t)__bfloat16_as_ushort(h1) << 16) | __bfloat16_as_ushort(h0);
        hp.y = ((uint32_t)__bfloat16_as_ushort(h3) << 16) | __bfloat16_as_ushort(h2);
        lp.x = ((uint32_t)__bfloat16_as_ushort(l1) << 16) | __bfloat16_as_ushort(l0);
        lp.y = ((uint32_t)__bfloat16_as_ushort(l3) << 16) | __bfloat16_as_ushort(l2);
        if (t < nx4){
            ((uint2*)g_xhi)[t] = hp; ((uint2*)g_xlo)[t] = lp;
        } else {
            ((uint2*)g_whi)[t - nx4] = hp; ((uint2*)g_wlo)[t - nx4] = lp;
        }
    }
}

// ---------------------------------------------------------------------------
// we/wr inducing-point projections (fp32, tiny)
// ---------------------------------------------------------------------------
__global__ void k_setup_wewr(const float* __restrict__ x,
                             const float* __restrict__ we_p,
                             const float* __restrict__ wr_p)
{
    int blk = blockIdx.x;
    int b = blk >> 4, h = blk & 15;
    int d = threadIdx.x;
    if (d >= D_) return;
    float xs[RM_];
#pragma unroll
    for (int m = 0; m < RM_; m++)
        xs[m] = x[((size_t)(b*N_ + c_idx[m]))*C_ + h*D_ + d];
#pragma unroll
    for (int a = 0; a < R_; a++){
        float se = 0.f, sr = 0.f;
#pragma unroll
        for (int m = 0; m < RM_; m++){
            se += xs[m] * we_p[(h*RM_ + m)*R_ + a];
            sr += xs[m] * wr_p[(h*RM_ + m)*R_ + a];
        }
        g_we[((b*H_ + h)*D_ + d)*R_ + a] = se;
        g_wr[((b*H_ + h)*D_ + d)*R_ + a] = sr;
    }
}

// ---------------------------------------------------------------------------
// S matrices + KL scalar
// ---------------------------------------------------------------------------
__global__ void k_setup_skl(const float* __restrict__ log_lam,
                            const float* __restrict__ m_u,
                            const float* __restrict__ s_tri,
                            const float* __restrict__ log_ssqrt,
                            float* __restrict__ kl_out)
{
    int t = threadIdx.x;
    for (int i = t; i < H_*R_*R_*R_; i += blockDim.x){
        int c = i % R_;
        int u = (i / R_) % R_;
        int a = (i / (R_*R_)) % R_;
        int h = i / (R_*R_*R_);
        float v = 0.f;
        if (u == c)      v = expf(log_ssqrt[(h*R_ + a)*R_ + u]);
        else if (u > c)  v = s_tri[((h*R_ + a)*R_ + u)*R_ + c];
        g_S[i] = v;
    }
    __shared__ float part[128];
    float p = 0.f;
    if (t < H_*R_){
        int h = t / R_, a = t % R_;
        float ll = log_lam[t];
        float e4 = expf(4.f*ll);
        float ss2 = 0.f;
        for (int u = 0; u < R_; u++){
            float dg = expf(log_ssqrt[(h*R_ + a)*R_ + u]);
            ss2 += dg*dg;
            for (int c = 0; c < u; c++){
                float v = s_tri[((h*R_ + a)*R_ + u)*R_ + c];
                ss2 += v*v;
            }
        }
        float mm = 0.f;
        for (int s = 0; s < R_; s++){
            float v = m_u[(h*R_ + a)*R_ + s];
            mm += v*v;
        }
        float lsum = 0.f;
        for (int u = 0; u < R_; u++) lsum += log_ssqrt[(h*R_ + a)*R_ + u];
        p = 0.5f*e4*(ss2 + mm) - lsum - 2.f*(float)R_*ll
            - (0.5f*(float)(R_*R_*H_)) / (float)(H_*R_);
    }
    part[t] = p;
    __syncthreads();
    if (t == 0){
        float s = 0.f;
        for (int i = 0; i < H_*R_; i++) s += part[i];
        *kl_out = s;
    }
}

// ---------------------------------------------------------------------------
// Fused main kernel: 128x128x1024 bf16-split mma.sync GEMM per CTA + epilogue
// 4-buffer cp.async ring, lookahead 2, ONE barrier per stage.
// ---------------------------------------------------------------------------
extern __shared__ char smem_raw[];

__global__ __launch_bounds__(256, 1)
void k_main(const float* __restrict__ mask,
            const float* __restrict__ eps,
            const float* __restrict__ log_lam,
            const float* __restrict__ m_u,
            const float* __restrict__ fw_w,
            const float* __restrict__ fw_b,
            float* __restrict__ out)
{
    const int nb = blockIdx.x, h = blockIdx.y, b = blockIdx.z;
    const int tid = threadIdx.x;
    const int wid = tid >> 5;
    const int lane = tid & 31;
    const uint32_t sb = smem_u32(smem_raw);

    __shared__ float we_s[D_*R_], wr_s[D_*R_], fww_s[D_*R_];
    __shared__ float S_s[R_*R_*R_], mu_s[R_*R_], lam2_s[R_], fwb_s[D_];

    {
        int base = (b*H_ + h)*D_*R_;
        for (int i = tid; i < D_*R_; i += 256){
            we_s[i] = g_we[base + i];
            wr_s[i] = g_wr[base + i];
            fww_s[i] = fw_w[i];
        }
        for (int i = tid; i < R_*R_*R_; i += 256) S_s[i] = g_S[h*R_*R_*R_ + i];
        for (int i = tid; i < R_*R_; i += 256)    mu_s[i] = m_u[h*R_*R_ + i];
        if (tid < R_)  lam2_s[tid] = expf(2.f*log_lam[h*R_ + tid]);
        if (tid < D_)  fwb_s[tid] = fw_b[tid];
    }

    const int rowA0 = b*N_ + nb*BM;

    // ---- cp.async load geometry: 8 chunks of 16B per thread per stage ----
    const __nv_bfloat16* gsrc[8];
    uint32_t soff[8];
#pragma unroll
    for (int i = 0; i < 8; i++){
        int c = i*256 + tid;
        int half = c >> 10;
        int term = (c >> 9) & 1;
        int row  = (c >> 2) & 127;
        int quad = c & 3;
        soff[i] = half*2*TERM_BYTES + term*TERM_BYTES + row*(ROWP*2) + quad*16;
        if (half == 0){
            const __nv_bfloat16* g = term ? g_xlo : g_xhi;
            gsrc[i] = g + ((size_t)(rowA0 + row))*C_ + quad*8;
        } else {
            int wj = (row < 64) ? (h*64 + row) : (C_ + h*64 + (row - 64));
            const __nv_bfloat16* g = term ? g_wlo : g_whi;
            gsrc[i] = g + (size_t)wj*C_ + quad*8;
        }
    }

    auto load_stage = [&](int kt, int buf){
        uint32_t stb = sb + buf*STAGE_BYTES;
#pragma unroll
        for (int i = 0; i < 8; i++)
            ldgsts16(stb + soff[i], gsrc[i] + kt*BK);
        cp_commit();
    };

    // ---- warp tile geometry ----
    const int wm = wid >> 2;        // 0/1 : m offset 64*wm
    const int wn = wid & 3;         // 0-3 : n offset 32*wn
    const int arow = lane & 15, acol8 = lane >> 4;

    uint32_t aoff[4][2], boff[2][2];
#pragma unroll
    for (int i = 0; i < 4; i++)
#pragma unroll
        for (int kk = 0; kk < 2; kk++)
            aoff[i][kk] = (wm*64 + i*16 + arow)*(ROWP*2) + (kk*16 + acol8*8)*2;
#pragma unroll
    for (int p = 0; p < 2; p++)
#pragma unroll
        for (int kk = 0; kk < 2; kk++)
            boff[p][kk] = (wn*32 + p*16 + arow)*(ROWP*2) + (kk*16 + acol8*8)*2;

    float acc[16][4];
#pragma unroll
    for (int i = 0; i < 16; i++)
#pragma unroll
        for (int j = 0; j < 4; j++) acc[i][j] = 0.f;

    // ---- pipeline: prologue loads stages 0,1 ----
    load_stage(0, 0);
    load_stage(1, 1);
    __syncthreads();   // also covers the shared-operand preload above

    for (int kt = 0; kt < NSTAGE; kt++){
        const int cur = kt & (NBUF-1);
        if (kt + 2 < NSTAGE){
            load_stage(kt + 2, (kt + 2) & (NBUF-1));
            cp_wait2();
        } else if (kt + 1 < NSTAGE){
            cp_wait1();
        } else {
            cp_wait0();
        }
        __syncthreads();   // single barrier per stage

        const uint32_t Ah = sb + cur*STAGE_BYTES;
        const uint32_t Al = Ah + TERM_BYTES;
        const uint32_t Bh = Ah + 2*TERM_BYTES;
        const uint32_t Bl = Ah + 3*TERM_BYTES;

#pragma unroll
        for (int kk = 0; kk < 2; kk++){
            uint32_t ah[4][4], al[4][4], bh[2][4], bl[2][4];
#pragma unroll
            for (int i = 0; i < 4; i++){
                ldm_x4(ah[i], Ah + aoff[i][kk]);
                ldm_x4(al[i], Al + aoff[i][kk]);
            }
#pragma unroll
            for (int p = 0; p < 2; p++){
                ldm_x4(bh[p], Bh + boff[p][kk]);
                ldm_x4(bl[p], Bl + boff[p][kk]);
            }
            // term-major: 16 independent MMAs between accumulator reuses
#pragma unroll
            for (int i = 0; i < 4; i++)
#pragma unroll
                for (int j = 0; j < 4; j++){
                    int p = j >> 1, s = j & 1;
                    mma_bf16(acc[i*4+j], ah[i], bh[p][s], bh[p][2+s]);
                }
#pragma unroll
            for (int i = 0; i < 4; i++)
#pragma unroll
                for (int j = 0; j < 4; j++){
                    int p = j >> 1, s = j & 1;
                    mma_bf16(acc[i*4+j], al[i], bh[p][s], bh[p][2+s]);
                }
#pragma unroll
            for (int i = 0; i < 4; i++)
#pragma unroll
                for (int j = 0; j < 4; j++){
                    int p = j >> 1, s = j & 1;
                    mma_bf16(acc[i*4+j], ah[i], bl[p][s], bl[p][2+s]);
                }
        }
        // no trailing barrier: next iteration writes buffer (kt+3)&3, which no
        // warp can still be reading (readers are at stages >= kt-1).
    }
    __syncthreads();   // all MMAs done before C-tile overwrite of stage buffers

    // ---- write C tile to smem (reuse stage buffers) ----
    float* Ct = (float*)smem_raw;
    {
        const int r0 = wm*64 + (lane >> 2);
        const int c0 = wn*32 + (lane & 3)*2;
#pragma unroll
        for (int i = 0; i < 4; i++)
#pragma unroll
            for (int j = 0; j < 4; j++){
                int rr = r0 + i*16, cc = c0 + j*8;
                Ct[rr*CP + cc]       = acc[i*4+j][0];
                Ct[rr*CP + cc + 1]   = acc[i*4+j][1];
                Ct[(rr+8)*CP + cc]   = acc[i*4+j][2];
                Ct[(rr+8)*CP + cc+1] = acc[i*4+j][3];
            }
    }
    __syncthreads();

    // ---- epilogue: one thread per row n ----
    if (tid < BM){
        const int n = nb*BM + tid;
        const float* row = Ct + tid*CP;
        const float mval = mask[b*N_ + n];

        float e[R_] = {0,0,0,0,0};
        float sq = 0.f;
        for (int d = 0; d < D_; d++){
            float qd = row[d];
            sq += qd*qd;
#pragma unroll
            for (int a = 0; a < R_; a++) e[a] += qd * we_s[d*R_ + a];
        }
        float sclq = mval / fmaxf(fabsf(mval)*sqrtf(sq), 1e-12f);

        float rr[R_] = {0,0,0,0,0};
        float sk = 0.f;
        for (int d = 0; d < D_; d++){
            float kd = row[D_ + d];
            sk += kd*kd;
#pragma unroll
            for (int a = 0; a < R_; a++) rr[a] += kd * wr_s[d*R_ + a];
        }
        float sclk = mval / fmaxf(fabsf(mval)*sqrtf(sk), 1e-12f);

        const size_t ebase = ((size_t)((b*H_ + h)*N_ + n))*R_;
        float es[R_], rs[R_], v1[R_];
#pragma unroll
        for (int a = 0; a < R_; a++){
            es[a] = e[a]*sclq;
            rs[a] = rr[a]*sclk;
            v1[a] = (es[a] + rs[a]) * lam2_s[a];
        }
        float* eo = out + ATTN_ELEMS + ebase;
        float* ro = out + ATTN_ELEMS + ESC_ELEMS + ebase;
#pragma unroll
        for (int a = 0; a < R_; a++){ eo[a] = es[a]; ro[a] = rs[a]; }

        float ev[R_];
#pragma unroll
        for (int u = 0; u < R_; u++) ev[u] = eps[ebase + u];
        float smp[R_];
#pragma unroll
        for (int s = 0; s < R_; s++){
            float am = 0.f;
#pragma unroll
            for (int a = 0; a < R_; a++) am += v1[a]*mu_s[a*R_ + s];
            smp[s] = am;
        }
#pragma unroll
        for (int a = 0; a < R_; a++)
#pragma unroll
            for (int u = 0; u < R_; u++){
                float f = v1[a]*ev[u];
#pragma unroll
                for (int c = 0; c < R_; c++)
                    smp[c] += f * S_s[(a*R_ + u)*R_ + c];
            }

        float* ob = out + ((size_t)(b*N_ + n))*C_ + h*D_;
#pragma unroll
        for (int d0 = 0; d0 < D_; d0 += 4){
            float4 o;
            float* op = (float*)&o;
#pragma unroll
            for (int dd = 0; dd < 4; dd++){
                float ao = fwb_s[d0 + dd];
#pragma unroll
                for (int a = 0; a < R_; a++) ao += smp[a]*fww_s[(d0 + dd)*R_ + a];
                op[dd] = ao;
            }
            *(float4*)(ob + d0) = o;
        }
    }
}

// ---------------------------------------------------------------------------
extern "C" void kernel_launch(void* const* d_in, const int* in_sizes, int n_in,
                              void* d_out, int out_size)
{
    const float* x         = (const float*)d_in[0];
    const float* mask      = (const float*)d_in[1];
    const float* eps       = (const float*)d_in[2];
    const float* qk_w      = (const float*)d_in[3];
    const float* we_p      = (const float*)d_in[4];
    const float* wr_p      = (const float*)d_in[5];
    const float* log_lam   = (const float*)d_in[6];
    const float* m_u       = (const float*)d_in[7];
    const float* s_tri     = (const float*)d_in[8];
    const float* log_ssqrt = (const float*)d_in[9];
    const float* fw_w      = (const float*)d_in[10];
    const float* fw_b      = (const float*)d_in[11];
    float* out = (float*)d_out;

    k_convert<<<4096, 256>>>(x, qk_w);
    k_setup_wewr<<<B_*H_, 64>>>(x, we_p, wr_p);
    k_setup_skl<<<1, 128>>>(log_lam, m_u, s_tri, log_ssqrt,
                            out + ATTN_ELEMS + 2*ESC_ELEMS);

    cudaFuncSetAttribute(k_main, cudaFuncAttributeMaxDynamicSharedMemorySize, SMEM_DYN);
    dim3 grid(N_/BM, H_, B_);
    k_main<<<grid, 256, SMEM_DYN>>>(mask, eps, log_lam, m_u, fw_w, fw_b, out);
}

// round 6
// speedup vs baseline: 2.5105x; 1.1061x over previous
#include <cuda_runtime.h>
#include <cuda_bf16.h>
#include <math.h>
#include <stdint.h>

#define B_ 8
#define N_ 2048
#define C_ 1024
#define H_ 16
#define D_ 64
#define R_ 5
#define RM_ 10

#define ATTN_ELEMS ((size_t)B_*N_*C_)              // 16777216
#define ESC_ELEMS  ((size_t)B_*H_*N_*R_)           // 1310720

// GEMM tiling
#define BM 128
#define BN 128
#define BK 32                 // K elems per stage
#define NSTAGE (C_/BK)        // 32
#define ROWP 40               // padded smem row stride in bf16 elems (80B)
#define TERM_BYTES (128*ROWP*2)          // one 128-row tile, 10240 B
#define STAGE_BYTES (4*TERM_BYTES)       // Ahi Alo Bhi Blo = 40960 B
#define NBUF 2
#define SMEM_DYN (NBUF*STAGE_BYTES)      // 81920 (>= 128*129*4=66048 C tile)
#define CP 129

// combined hi/lo scratch: one base pointer, uint32 element offsets
#define XN ((uint32_t)(B_*N_*C_))        // 16777216
#define WN ((uint32_t)(2*C_*C_))         // 2097152
#define OFF_XHI 0u
#define OFF_WHI XN
#define OFF_XLO (XN + WN)
#define OFF_WLO (2u*XN + WN)

__device__ __align__(256) __nv_bfloat16 g_hilo[2*(size_t)(XN + WN)];
__device__ float g_we[B_*H_*D_*R_];
__device__ float g_wr[B_*H_*D_*R_];
__device__ float g_S[H_*R_*R_*R_];

__constant__ int c_idx[RM_] = {0,227,454,682,909,1137,1364,1592,1819,2047};

// ---------------- PTX helpers (all baseline / portable) ----------------
__device__ __forceinline__ uint32_t smem_u32(const void* p){
    uint32_t a;
    asm("{ .reg .u64 t; cvta.to.shared.u64 t, %1; cvt.u32.u64 %0, t; }" : "=r"(a) : "l"(p));
    return a;
}
__device__ __forceinline__ void ldgsts16(uint32_t dst, const void* src){
    asm volatile("cp.async.cg.shared.global [%0], [%1], 16;" :: "r"(dst), "l"(src));
}
__device__ __forceinline__ void cp_commit(){ asm volatile("cp.async.commit_group;" ::: "memory"); }
__device__ __forceinline__ void cp_wait1(){ asm volatile("cp.async.wait_group 1;" ::: "memory"); }
__device__ __forceinline__ void cp_wait0(){ asm volatile("cp.async.wait_group 0;" ::: "memory"); }

__device__ __forceinline__ void ldm_x4(uint32_t* r, uint32_t addr){
    asm volatile("ldmatrix.sync.aligned.m8n8.x4.shared.b16 {%0,%1,%2,%3}, [%4];"
        : "=r"(r[0]),"=r"(r[1]),"=r"(r[2]),"=r"(r[3]) : "r"(addr));
}
__device__ __forceinline__ void mma_bf16(float* d, const uint32_t* a, uint32_t b0, uint32_t b1){
    asm volatile("mma.sync.aligned.m16n8k16.row.col.f32.bf16.bf16.f32 "
        "{%0,%1,%2,%3}, {%4,%5,%6,%7}, {%8,%9}, {%0,%1,%2,%3};"
        : "+f"(d[0]),"+f"(d[1]),"+f"(d[2]),"+f"(d[3])
        : "r"(a[0]),"r"(a[1]),"r"(a[2]),"r"(a[3]), "r"(b0),"r"(b1));
}

// ---------------------------------------------------------------------------
// Convert fp32 -> bf16 hi/lo split for x and qk_w into g_hilo
// ---------------------------------------------------------------------------
__global__ void k_convert(const float* __restrict__ x, const float* __restrict__ qk_w)
{
    const size_t nx4 = (size_t)XN/4;
    const size_t nw4 = (size_t)WN/4;
    const size_t tot = nx4 + nw4;
    size_t stride = (size_t)gridDim.x*blockDim.x;
    uint2* g4 = (uint2*)g_hilo;
    for (size_t t = (size_t)blockIdx.x*blockDim.x + threadIdx.x; t < tot; t += stride){
        float4 v = (t < nx4) ? ((const float4*)x)[t] : ((const float4*)qk_w)[t - nx4];
        __nv_bfloat16 h0 = __float2bfloat16_rn(v.x);
        __nv_bfloat16 h1 = __float2bfloat16_rn(v.y);
        __nv_bfloat16 h2 = __float2bfloat16_rn(v.z);
        __nv_bfloat16 h3 = __float2bfloat16_rn(v.w);
        __nv_bfloat16 l0 = __float2bfloat16_rn(v.x - __bfloat162float(h0));
        __nv_bfloat16 l1 = __float2bfloat16_rn(v.y - __bfloat162float(h1));
        __nv_bfloat16 l2 = __float2bfloat16_rn(v.z - __bfloat162float(h2));
        __nv_bfloat16 l3 = __float2bfloat16_rn(v.w - __bfloat162float(h3));
        uint2 hp, lp;
        hp.x = ((uint32_t)__bfloat16_as_ushort(h1) << 16) | __bfloat16_as_ushort(h0);
        hp.y = ((uint32_t)__bfloat16_as_ushort(h3) << 16) | __bfloat16_as_ushort(h2);
        lp.x = ((uint32_t)__bfloat16_as_ushort(l1) << 16) | __bfloat16_as_ushort(l0);
        lp.y = ((uint32_t)__bfloat16_as_ushort(l3) << 16) | __bfloat16_as_ushort(l2);
        if (t < nx4){
            g4[OFF_XHI/4 + t] = hp;
            g4[OFF_XLO/4 + t] = lp;
        } else {
            size_t w = t - nx4;
            g4[OFF_WHI/4 + w] = hp;
            g4[OFF_WLO/4 + w] = lp;
        }
    }
}

// ---------------------------------------------------------------------------
// we/wr inducing-point projections (fp32, tiny)
// ---------------------------------------------------------------------------
__global__ void k_setup_wewr(const float* __restrict__ x,
                             const float* __restrict__ we_p,
                             const float* __restrict__ wr_p)
{
    int blk = blockIdx.x;
    int b = blk >> 4, h = blk & 15;
    int d = threadIdx.x;
    if (d >= D_) return;
    float xs[RM_];
#pragma unroll
    for (int m = 0; m < RM_; m++)
        xs[m] = x[((size_t)(b*N_ + c_idx[m]))*C_ + h*D_ + d];
#pragma unroll
    for (int a = 0; a < R_; a++){
        float se = 0.f, sr = 0.f;
#pragma unroll
        for (int m = 0; m < RM_; m++){
            se += xs[m] * we_p[(h*RM_ + m)*R_ + a];
            sr += xs[m] * wr_p[(h*RM_ + m)*R_ + a];
        }
        g_we[((b*H_ + h)*D_ + d)*R_ + a] = se;
        g_wr[((b*H_ + h)*D_ + d)*R_ + a] = sr;
    }
}

// ---------------------------------------------------------------------------
// S matrices + KL scalar
// ---------------------------------------------------------------------------
__global__ void k_setup_skl(const float* __restrict__ log_lam,
                            const float* __restrict__ m_u,
                            const float* __restrict__ s_tri,
                            const float* __restrict__ log_ssqrt,
                            float* __restrict__ kl_out)
{
    int t = threadIdx.x;
    for (int i = t; i < H_*R_*R_*R_; i += blockDim.x){
        int c = i % R_;
        int u = (i / R_) % R_;
        int a = (i / (R_*R_)) % R_;
        int h = i / (R_*R_*R_);
        float v = 0.f;
        if (u == c)      v = expf(log_ssqrt[(h*R_ + a)*R_ + u]);
        else if (u > c)  v = s_tri[((h*R_ + a)*R_ + u)*R_ + c];
        g_S[i] = v;
    }
    __shared__ float part[128];
    float p = 0.f;
    if (t < H_*R_){
        int h = t / R_, a = t % R_;
        float ll = log_lam[t];
        float e4 = expf(4.f*ll);
        float ss2 = 0.f;
        for (int u = 0; u < R_; u++){
            float dg = expf(log_ssqrt[(h*R_ + a)*R_ + u]);
            ss2 += dg*dg;
            for (int c = 0; c < u; c++){
                float v = s_tri[((h*R_ + a)*R_ + u)*R_ + c];
                ss2 += v*v;
            }
        }
        float mm = 0.f;
        for (int s = 0; s < R_; s++){
            float v = m_u[(h*R_ + a)*R_ + s];
            mm += v*v;
        }
        float lsum = 0.f;
        for (int u = 0; u < R_; u++) lsum += log_ssqrt[(h*R_ + a)*R_ + u];
        p = 0.5f*e4*(ss2 + mm) - lsum - 2.f*(float)R_*ll
            - (0.5f*(float)(R_*R_*H_)) / (float)(H_*R_);
    }
    part[t] = p;
    __syncthreads();
    if (t == 0){
        float s = 0.f;
        for (int i = 0; i < H_*R_; i++) s += part[i];
        *kl_out = s;
    }
}

// ---------------------------------------------------------------------------
// Fused main kernel: 128x128x1024 bf16-split mma.sync GEMM per CTA + epilogue
// NBUF=2 double buffer, 2 CTAs/SM (regs<=128, smem 80KB).
// ---------------------------------------------------------------------------
extern __shared__ char smem_raw[];

__global__ __launch_bounds__(256, 2)
void k_main(const float* __restrict__ mask,
            const float* __restrict__ eps,
            const float* __restrict__ log_lam,
            const float* __restrict__ m_u,
            const float* __restrict__ fw_w,
            const float* __restrict__ fw_b,
            float* __restrict__ out)
{
    const int nb = blockIdx.x, h = blockIdx.y, b = blockIdx.z;
    const int tid = threadIdx.x;
    const int wid = tid >> 5;
    const int lane = tid & 31;
    const uint32_t sb = smem_u32(smem_raw);

    __shared__ float we_s[D_*R_], wr_s[D_*R_], fww_s[D_*R_];
    __shared__ float S_s[R_*R_*R_], mu_s[R_*R_], lam2_s[R_], fwb_s[D_];

    {
        int base = (b*H_ + h)*D_*R_;
        for (int i = tid; i < D_*R_; i += 256){
            we_s[i] = g_we[base + i];
            wr_s[i] = g_wr[base + i];
            fww_s[i] = fw_w[i];
        }
        for (int i = tid; i < R_*R_*R_; i += 256) S_s[i] = g_S[h*R_*R_*R_ + i];
        for (int i = tid; i < R_*R_; i += 256)    mu_s[i] = m_u[h*R_*R_ + i];
        if (tid < R_)  lam2_s[tid] = expf(2.f*log_lam[h*R_ + tid]);
        if (tid < D_)  fwb_s[tid] = fw_b[tid];
    }

    const int rowA0 = b*N_ + nb*BM;

    // ---- cp.async load geometry: 8 chunks of 16B per thread per stage ----
    // all sources are element offsets (uint32) into the single g_hilo buffer
    uint32_t goff[8];
    uint32_t soff[8];
#pragma unroll
    for (int i = 0; i < 8; i++){
        int c = i*256 + tid;
        int half = c >> 10;
        int term = (c >> 9) & 1;
        int row  = (c >> 2) & 127;
        int quad = c & 3;
        soff[i] = half*2*TERM_BYTES + term*TERM_BYTES + row*(ROWP*2) + quad*16;
        if (half == 0){
            goff[i] = (term ? OFF_XLO : OFF_XHI) + (uint32_t)(rowA0 + row)*C_ + quad*8;
        } else {
            int wj = (row < 64) ? (h*64 + row) : (C_ + h*64 + (row - 64));
            goff[i] = (term ? OFF_WLO : OFF_WHI) + (uint32_t)wj*C_ + quad*8;
        }
    }

    auto load_stage = [&](int kt, int buf){
        uint32_t stb = sb + buf*STAGE_BYTES;
        uint32_t ke = (uint32_t)kt*BK;
#pragma unroll
        for (int i = 0; i < 8; i++)
            ldgsts16(stb + soff[i], g_hilo + (size_t)(goff[i] + ke));
        cp_commit();
    };

    // ---- warp tile geometry (64x32 per warp, 2x4 grid) ----
    const int wm = wid >> 2;
    const int wn = wid & 3;
    const int arow = lane & 15, acol8 = lane >> 4;

    uint32_t aoff[4], boff[2];
#pragma unroll
    for (int i = 0; i < 4; i++)
        aoff[i] = (wm*64 + i*16 + arow)*(ROWP*2) + acol8*16;
#pragma unroll
    for (int p = 0; p < 2; p++)
        boff[p] = (wn*32 + p*16 + arow)*(ROWP*2) + acol8*16;

    float acc[16][4];
#pragma unroll
    for (int i = 0; i < 16; i++)
#pragma unroll
        for (int j = 0; j < 4; j++) acc[i][j] = 0.f;

    // ---- pipeline: NBUF=2 double buffer, two barriers per stage ----
    load_stage(0, 0);
    __syncthreads();   // also covers shared-operand preload

    for (int kt = 0; kt < NSTAGE; kt++){
        const int cur = kt & 1;
        if (kt + 1 < NSTAGE){
            load_stage(kt + 1, cur ^ 1);
            cp_wait1();
        } else {
            cp_wait0();
        }
        __syncthreads();

        const uint32_t Ah = sb + cur*STAGE_BYTES;
        const uint32_t Al = Ah + TERM_BYTES;
        const uint32_t Bh = Ah + 2*TERM_BYTES;
        const uint32_t Bl = Ah + 3*TERM_BYTES;

#pragma unroll
        for (int kk = 0; kk < 2; kk++){
            const uint32_t kb = kk*32;
            uint32_t ah[4][4], bh[2][4];
#pragma unroll
            for (int i = 0; i < 4; i++) ldm_x4(ah[i], Ah + aoff[i] + kb);
#pragma unroll
            for (int p = 0; p < 2; p++) ldm_x4(bh[p], Bh + boff[p] + kb);
            // hh term
#pragma unroll
            for (int i = 0; i < 4; i++)
#pragma unroll
                for (int j = 0; j < 4; j++){
                    int p = j >> 1, s = j & 1;
                    mma_bf16(acc[i*4+j], ah[i], bh[p][s], bh[p][2+s]);
                }
            // lh term (al loaded here; ah stays live for hl)
            {
                uint32_t al[4][4];
#pragma unroll
                for (int i = 0; i < 4; i++) ldm_x4(al[i], Al + aoff[i] + kb);
#pragma unroll
                for (int i = 0; i < 4; i++)
#pragma unroll
                    for (int j = 0; j < 4; j++){
                        int p = j >> 1, s = j & 1;
                        mma_bf16(acc[i*4+j], al[i], bh[p][s], bh[p][2+s]);
                    }
            }
            // hl term
            {
                uint32_t bl[2][4];
#pragma unroll
                for (int p = 0; p < 2; p++) ldm_x4(bl[p], Bl + boff[p] + kb);
#pragma unroll
                for (int i = 0; i < 4; i++)
#pragma unroll
                    for (int j = 0; j < 4; j++){
                        int p = j >> 1, s = j & 1;
                        mma_bf16(acc[i*4+j], ah[i], bl[p][s], bl[p][2+s]);
                    }
            }
        }
        __syncthreads();   // all reads of 'cur' done before next refill
    }

    // ---- write C tile to smem (reuse stage buffers) ----
    float* Ct = (float*)smem_raw;
    {
        const int r0 = wm*64 + (lane >> 2);
        const int c0 = wn*32 + (lane & 3)*2;
#pragma unroll
        for (int i = 0; i < 4; i++)
#pragma unroll
            for (int j = 0; j < 4; j++){
                int rr = r0 + i*16, cc = c0 + j*8;
                Ct[rr*CP + cc]       = acc[i*4+j][0];
                Ct[rr*CP + cc + 1]   = acc[i*4+j][1];
                Ct[(rr+8)*CP + cc]   = acc[i*4+j][2];
                Ct[(rr+8)*CP + cc+1] = acc[i*4+j][3];
            }
    }
    __syncthreads();

    // ---- epilogue: one thread per row n ----
    if (tid < BM){
        const int n = nb*BM + tid;
        const float* row = Ct + tid*CP;
        const float mval = mask[b*N_ + n];

        float e[R_] = {0,0,0,0,0};
        float sq = 0.f;
        for (int d = 0; d < D_; d++){
            float qd = row[d];
            sq += qd*qd;
#pragma unroll
            for (int a = 0; a < R_; a++) e[a] += qd * we_s[d*R_ + a];
        }
        float sclq = mval / fmaxf(fabsf(mval)*sqrtf(sq), 1e-12f);

        float rr[R_] = {0,0,0,0,0};
        float sk = 0.f;
        for (int d = 0; d < D_; d++){
            float kd = row[D_ + d];
            sk += kd*kd;
#pragma unroll
            for (int a = 0; a < R_; a++) rr[a] += kd * wr_s[d*R_ + a];
        }
        float sclk = mval / fmaxf(fabsf(mval)*sqrtf(sk), 1e-12f);

        const size_t ebase = ((size_t)((b*H_ + h)*N_ + n))*R_;
        float es[R_], rs[R_], v1[R_];
#pragma unroll
        for (int a = 0; a < R_; a++){
            es[a] = e[a]*sclq;
            rs[a] = rr[a]*sclk;
            v1[a] = (es[a] + rs[a]) * lam2_s[a];
        }
        float* eo = out + ATTN_ELEMS + ebase;
        float* ro = out + ATTN_ELEMS + ESC_ELEMS + ebase;
#pragma unroll
        for (int a = 0; a < R_; a++){ eo[a] = es[a]; ro[a] = rs[a]; }

        float ev[R_];
#pragma unroll
        for (int u = 0; u < R_; u++) ev[u] = eps[ebase + u];
        float smp[R_];
#pragma unroll
        for (int s = 0; s < R_; s++){
            float am = 0.f;
#pragma unroll
            for (int a = 0; a < R_; a++) am += v1[a]*mu_s[a*R_ + s];
            smp[s] = am;
        }
#pragma unroll
        for (int a = 0; a < R_; a++)
#pragma unroll
            for (int u = 0; u < R_; u++){
                float f = v1[a]*ev[u];
#pragma unroll
                for (int c = 0; c < R_; c++)
                    smp[c] += f * S_s[(a*R_ + u)*R_ + c];
            }

        float* ob = out + ((size_t)(b*N_ + n))*C_ + h*D_;
#pragma unroll
        for (int d0 = 0; d0 < D_; d0 += 4){
            float4 o;
            float* op = (float*)&o;
#pragma unroll
            for (int dd = 0; dd < 4; dd++){
                float ao = fwb_s[d0 + dd];
#pragma unroll
                for (int a = 0; a < R_; a++) ao += smp[a]*fww_s[(d0 + dd)*R_ + a];
                op[dd] = ao;
            }
            *(float4*)(ob + d0) = o;
        }
    }
}

// ---------------------------------------------------------------------------
extern "C" void kernel_launch(void* const* d_in, const int* in_sizes, int n_in,
                              void* d_out, int out_size)
{
    const float* x         = (const float*)d_in[0];
    const float* mask      = (const float*)d_in[1];
    const float* eps       = (const float*)d_in[2];
    const float* qk_w      = (const float*)d_in[3];
    const float* we_p      = (const float*)d_in[4];
    const float* wr_p      = (const float*)d_in[5];
    const float* log_lam   = (const float*)d_in[6];
    const float* m_u       = (const float*)d_in[7];
    const float* s_tri     = (const float*)d_in[8];
    const float* log_ssqrt = (const float*)d_in[9];
    const float* fw_w      = (const float*)d_in[10];
    const float* fw_b      = (const float*)d_in[11];
    float* out = (float*)d_out;

    k_convert<<<4096, 256>>>(x, qk_w);
    k_setup_wewr<<<B_*H_, 64>>>(x, we_p, wr_p);
    k_setup_skl<<<1, 128>>>(log_lam, m_u, s_tri, log_ssqrt,
                            out + ATTN_ELEMS + 2*ESC_ELEMS);

    cudaFuncSetAttribute(k_main, cudaFuncAttributeMaxDynamicSharedMemorySize, SMEM_DYN);
    dim3 grid(N_/BM, H_, B_);
    k_main<<<grid, 256, SMEM_DYN>>>(mask, eps, log_lam, m_u, fw_w, fw_b, out);
}

// round 7
// speedup vs baseline: 3.3836x; 1.3478x over previous
#include <cuda_runtime.h>
#include <cuda_fp16.h>
#include <math.h>
#include <stdint.h>

#define B_ 8
#define N_ 2048
#define C_ 1024
#define H_ 16
#define D_ 64
#define R_ 5
#define RM_ 10

#define ATTN_ELEMS ((size_t)B_*N_*C_)              // 16777216
#define ESC_ELEMS  ((size_t)B_*H_*N_*R_)           // 1310720

// GEMM tiling
#define BM 128
#define BN 128
#define BK 32                 // K elems per stage
#define NSTAGE (C_/BK)        // 32
#define ROWP 40               // padded smem row stride in fp16 elems (80B)
#define TERM_BYTES (128*ROWP*2)          // one 128-row tile, 10240 B
#define STAGE_BYTES (3*TERM_BYTES)       // Ahi Alo Bhi = 30720 B
#define NBUF 2
#define CP 129
#define SMEM_DYN (BM*CP*4)               // 66048 (>= NBUF*STAGE_BYTES = 61440)

// combined scratch: one base pointer, uint32 element offsets
#define XN ((uint32_t)(B_*N_*C_))        // 16777216
#define WN ((uint32_t)(2*C_*C_))         // 2097152
#define OFF_XHI 0u
#define OFF_WHI XN
#define OFF_XLO (XN + WN)

__device__ __align__(256) __half g_hl[(size_t)(2u*XN + WN)];
__device__ float g_we[B_*H_*D_*R_];
__device__ float g_wr[B_*H_*D_*R_];
__device__ float g_S[H_*R_*R_*R_];

__constant__ int c_idx[RM_] = {0,227,454,682,909,1137,1364,1592,1819,2047};

// ---------------- PTX helpers (all baseline / portable) ----------------
__device__ __forceinline__ uint32_t smem_u32(const void* p){
    uint32_t a;
    asm("{ .reg .u64 t; cvta.to.shared.u64 t, %1; cvt.u32.u64 %0, t; }" : "=r"(a) : "l"(p));
    return a;
}
__device__ __forceinline__ void ldgsts16(uint32_t dst, const void* src){
    asm volatile("cp.async.cg.shared.global [%0], [%1], 16;" :: "r"(dst), "l"(src));
}
__device__ __forceinline__ void cp_commit(){ asm volatile("cp.async.commit_group;" ::: "memory"); }
__device__ __forceinline__ void cp_wait1(){ asm volatile("cp.async.wait_group 1;" ::: "memory"); }
__device__ __forceinline__ void cp_wait0(){ asm volatile("cp.async.wait_group 0;" ::: "memory"); }

__device__ __forceinline__ void ldm_x4(uint32_t* r, uint32_t addr){
    asm volatile("ldmatrix.sync.aligned.m8n8.x4.shared.b16 {%0,%1,%2,%3}, [%4];"
        : "=r"(r[0]),"=r"(r[1]),"=r"(r[2]),"=r"(r[3]) : "r"(addr));
}
__device__ __forceinline__ void mma_f16(float* d, const uint32_t* a, uint32_t b0, uint32_t b1){
    asm volatile("mma.sync.aligned.m16n8k16.row.col.f32.f16.f16.f32 "
        "{%0,%1,%2,%3}, {%4,%5,%6,%7}, {%8,%9}, {%0,%1,%2,%3};"
        : "+f"(d[0]),"+f"(d[1]),"+f"(d[2]),"+f"(d[3])
        : "r"(a[0]),"r"(a[1]),"r"(a[2]),"r"(a[3]), "r"(b0),"r"(b1));
}

// ---------------------------------------------------------------------------
// Convert fp32 -> fp16 hi/lo split for x, hi-only for qk_w
// ---------------------------------------------------------------------------
__global__ void k_convert(const float* __restrict__ x, const float* __restrict__ qk_w)
{
    const size_t nx4 = (size_t)XN/4;
    const size_t nw4 = (size_t)WN/4;
    const size_t tot = nx4 + nw4;
    size_t stride = (size_t)gridDim.x*blockDim.x;
    uint2* g4 = (uint2*)g_hl;
    for (size_t t = (size_t)blockIdx.x*blockDim.x + threadIdx.x; t < tot; t += stride){
        if (t < nx4){
            float4 v = ((const float4*)x)[t];
            __half h0 = __float2half_rn(v.x);
            __half h1 = __float2half_rn(v.y);
            __half h2 = __float2half_rn(v.z);
            __half h3 = __float2half_rn(v.w);
            __half l0 = __float2half_rn(v.x - __half2float(h0));
            __half l1 = __float2half_rn(v.y - __half2float(h1));
            __half l2 = __float2half_rn(v.z - __half2float(h2));
            __half l3 = __float2half_rn(v.w - __half2float(h3));
            uint2 hp, lp;
            hp.x = ((uint32_t)__half_as_ushort(h1) << 16) | __half_as_ushort(h0);
            hp.y = ((uint32_t)__half_as_ushort(h3) << 16) | __half_as_ushort(h2);
            lp.x = ((uint32_t)__half_as_ushort(l1) << 16) | __half_as_ushort(l0);
            lp.y = ((uint32_t)__half_as_ushort(l3) << 16) | __half_as_ushort(l2);
            g4[OFF_XHI/4 + t] = hp;
            g4[OFF_XLO/4 + t] = lp;
        } else {
            size_t w = t - nx4;
            float4 v = ((const float4*)qk_w)[w];
            uint2 hp;
            hp.x = ((uint32_t)__half_as_ushort(__float2half_rn(v.y)) << 16)
                 | __half_as_ushort(__float2half_rn(v.x));
            hp.y = ((uint32_t)__half_as_ushort(__float2half_rn(v.w)) << 16)
                 | __half_as_ushort(__float2half_rn(v.z));
            g4[OFF_WHI/4 + w] = hp;
        }
    }
}

// ---------------------------------------------------------------------------
// we/wr inducing-point projections (fp32, tiny)
// ---------------------------------------------------------------------------
__global__ void k_setup_wewr(const float* __restrict__ x,
                             const float* __restrict__ we_p,
                             const float* __restrict__ wr_p)
{
    int blk = blockIdx.x;
    int b = blk >> 4, h = blk & 15;
    int d = threadIdx.x;
    if (d >= D_) return;
    float xs[RM_];
#pragma unroll
    for (int m = 0; m < RM_; m++)
        xs[m] = x[((size_t)(b*N_ + c_idx[m]))*C_ + h*D_ + d];
#pragma unroll
    for (int a = 0; a < R_; a++){
        float se = 0.f, sr = 0.f;
#pragma unroll
        for (int m = 0; m < RM_; m++){
            se += xs[m] * we_p[(h*RM_ + m)*R_ + a];
            sr += xs[m] * wr_p[(h*RM_ + m)*R_ + a];
        }
        g_we[((b*H_ + h)*D_ + d)*R_ + a] = se;
        g_wr[((b*H_ + h)*D_ + d)*R_ + a] = sr;
    }
}

// ---------------------------------------------------------------------------
// S matrices + KL scalar
// ---------------------------------------------------------------------------
__global__ void k_setup_skl(const float* __restrict__ log_lam,
                            const float* __restrict__ m_u,
                            const float* __restrict__ s_tri,
                            const float* __restrict__ log_ssqrt,
                            float* __restrict__ kl_out)
{
    int t = threadIdx.x;
    for (int i = t; i < H_*R_*R_*R_; i += blockDim.x){
        int c = i % R_;
        int u = (i / R_) % R_;
        int a = (i / (R_*R_)) % R_;
        int h = i / (R_*R_*R_);
        float v = 0.f;
        if (u == c)      v = expf(log_ssqrt[(h*R_ + a)*R_ + u]);
        else if (u > c)  v = s_tri[((h*R_ + a)*R_ + u)*R_ + c];
        g_S[i] = v;
    }
    __shared__ float part[128];
    float p = 0.f;
    if (t < H_*R_){
        int h = t / R_, a = t % R_;
        float ll = log_lam[t];
        float e4 = expf(4.f*ll);
        float ss2 = 0.f;
        for (int u = 0; u < R_; u++){
            float dg = expf(log_ssqrt[(h*R_ + a)*R_ + u]);
            ss2 += dg*dg;
            for (int c = 0; c < u; c++){
                float v = s_tri[((h*R_ + a)*R_ + u)*R_ + c];
                ss2 += v*v;
            }
        }
        float mm = 0.f;
        for (int s = 0; s < R_; s++){
            float v = m_u[(h*R_ + a)*R_ + s];
            mm += v*v;
        }
        float lsum = 0.f;
        for (int u = 0; u < R_; u++) lsum += log_ssqrt[(h*R_ + a)*R_ + u];
        p = 0.5f*e4*(ss2 + mm) - lsum - 2.f*(float)R_*ll
            - (0.5f*(float)(R_*R_*H_)) / (float)(H_*R_);
    }
    part[t] = p;
    __syncthreads();
    if (t == 0){
        float s = 0.f;
        for (int i = 0; i < H_*R_; i++) s += part[i];
        *kl_out = s;
    }
}

// ---------------------------------------------------------------------------
// Fused main kernel: 128x128x1024 fp16-split (2-term) mma.sync GEMM + epilogue
// NBUF=2 double buffer, 2 CTAs/SM.
// ---------------------------------------------------------------------------
extern __shared__ char smem_raw[];

__global__ __launch_bounds__(256, 2)
void k_main(const float* __restrict__ mask,
            const float* __restrict__ eps,
            const float* __restrict__ log_lam,
            const float* __restrict__ m_u,
            const float* __restrict__ fw_w,
            const float* __restrict__ fw_b,
            float* __restrict__ out)
{
    const int nb = blockIdx.x, h = blockIdx.y, b = blockIdx.z;
    const int tid = threadIdx.x;
    const int wid = tid >> 5;
    const int lane = tid & 31;
    const uint32_t sb = smem_u32(smem_raw);

    __shared__ float we_s[D_*R_], wr_s[D_*R_], fww_s[D_*R_];
    __shared__ float S_s[R_*R_*R_], mu_s[R_*R_], lam2_s[R_], fwb_s[D_];

    {
        int base = (b*H_ + h)*D_*R_;
        for (int i = tid; i < D_*R_; i += 256){
            we_s[i] = g_we[base + i];
            wr_s[i] = g_wr[base + i];
            fww_s[i] = fw_w[i];
        }
        for (int i = tid; i < R_*R_*R_; i += 256) S_s[i] = g_S[h*R_*R_*R_ + i];
        for (int i = tid; i < R_*R_; i += 256)    mu_s[i] = m_u[h*R_*R_ + i];
        if (tid < R_)  lam2_s[tid] = expf(2.f*log_lam[h*R_ + tid]);
        if (tid < D_)  fwb_s[tid] = fw_b[tid];
    }

    const int rowA0 = b*N_ + nb*BM;

    // ---- cp.async load geometry: 6 chunks of 16B per thread per stage ----
    // chunk c = i*256 + tid: tile=c/512 (0=Ahi,1=Alo,2=Bhi), row=(c%512)/4, quad=c%4
    uint32_t goff[6];
    uint32_t soff[6];
#pragma unroll
    for (int i = 0; i < 6; i++){
        int c = i*256 + tid;
        int tile = c >> 9;
        int row  = (c >> 2) & 127;
        int quad = c & 3;
        soff[i] = tile*TERM_BYTES + row*(ROWP*2) + quad*16;
        if (tile == 0)
            goff[i] = OFF_XHI + (uint32_t)(rowA0 + row)*C_ + quad*8;
        else if (tile == 1)
            goff[i] = OFF_XLO + (uint32_t)(rowA0 + row)*C_ + quad*8;
        else {
            int wj = (row < 64) ? (h*64 + row) : (C_ + h*64 + (row - 64));
            goff[i] = OFF_WHI + (uint32_t)wj*C_ + quad*8;
        }
    }

    auto load_stage = [&](int kt, int buf){
        uint32_t stb = sb + buf*STAGE_BYTES;
        uint32_t ke = (uint32_t)kt*BK;
#pragma unroll
        for (int i = 0; i < 6; i++)
            ldgsts16(stb + soff[i], g_hl + (size_t)(goff[i] + ke));
        cp_commit();
    };

    // ---- warp tile geometry (64x32 per warp, 2x4 grid) ----
    const int wm = wid >> 2;
    const int wn = wid & 3;
    const int arow = lane & 15, acol8 = lane >> 4;

    uint32_t aoff[4], boff[2];
#pragma unroll
    for (int i = 0; i < 4; i++)
        aoff[i] = (wm*64 + i*16 + arow)*(ROWP*2) + acol8*16;
#pragma unroll
    for (int p = 0; p < 2; p++)
        boff[p] = (wn*32 + p*16 + arow)*(ROWP*2) + acol8*16;

    float acc[16][4];
#pragma unroll
    for (int i = 0; i < 16; i++)
#pragma unroll
        for (int j = 0; j < 4; j++) acc[i][j] = 0.f;

    // ---- pipeline: NBUF=2 double buffer ----
    load_stage(0, 0);
    __syncthreads();   // also covers shared-operand preload

    for (int kt = 0; kt < NSTAGE; kt++){
        const int cur = kt & 1;
        if (kt + 1 < NSTAGE){
            load_stage(kt + 1, cur ^ 1);
            cp_wait1();
        } else {
            cp_wait0();
        }
        __syncthreads();

        const uint32_t Ah = sb + cur*STAGE_BYTES;
        const uint32_t Al = Ah + TERM_BYTES;
        const uint32_t Bh = Ah + 2*TERM_BYTES;

#pragma unroll
        for (int kk = 0; kk < 2; kk++){
            const uint32_t kb = kk*32;
            uint32_t ah[4][4], bh[2][4];
#pragma unroll
            for (int i = 0; i < 4; i++) ldm_x4(ah[i], Ah + aoff[i] + kb);
#pragma unroll
            for (int p = 0; p < 2; p++) ldm_x4(bh[p], Bh + boff[p] + kb);
            // hh term
#pragma unroll
            for (int i = 0; i < 4; i++)
#pragma unroll
                for (int j = 0; j < 4; j++){
                    int p = j >> 1, s = j & 1;
                    mma_f16(acc[i*4+j], ah[i], bh[p][s], bh[p][2+s]);
                }
            // lh term
            {
                uint32_t al[4][4];
#pragma unroll
                for (int i = 0; i < 4; i++) ldm_x4(al[i], Al + aoff[i] + kb);
#pragma unroll
                for (int i = 0; i < 4; i++)
#pragma unroll
                    for (int j = 0; j < 4; j++){
                        int p = j >> 1, s = j & 1;
                        mma_f16(acc[i*4+j], al[i], bh[p][s], bh[p][2+s]);
                    }
            }
        }
        __syncthreads();   // all reads of 'cur' done before next refill
    }

    // ---- write C tile to smem (reuse stage buffers) ----
    float* Ct = (float*)smem_raw;
    {
        const int r0 = wm*64 + (lane >> 2);
        const int c0 = wn*32 + (lane & 3)*2;
#pragma unroll
        for (int i = 0; i < 4; i++)
#pragma unroll
            for (int j = 0; j < 4; j++){
                int rr = r0 + i*16, cc = c0 + j*8;
                Ct[rr*CP + cc]       = acc[i*4+j][0];
                Ct[rr*CP + cc + 1]   = acc[i*4+j][1];
                Ct[(rr+8)*CP + cc]   = acc[i*4+j][2];
                Ct[(rr+8)*CP + cc+1] = acc[i*4+j][3];
            }
    }
    __syncthreads();

    // ---- epilogue: one thread per row n ----
    if (tid < BM){
        const int n = nb*BM + tid;
        const float* row = Ct + tid*CP;
        const float mval = mask[b*N_ + n];

        float e[R_] = {0,0,0,0,0};
        float sq = 0.f;
        for (int d = 0; d < D_; d++){
            float qd = row[d];
            sq += qd*qd;
#pragma unroll
            for (int a = 0; a < R_; a++) e[a] += qd * we_s[d*R_ + a];
        }
        float sclq = mval / fmaxf(fabsf(mval)*sqrtf(sq), 1e-12f);

        float rr[R_] = {0,0,0,0,0};
        float sk = 0.f;
        for (int d = 0; d < D_; d++){
            float kd = row[D_ + d];
            sk += kd*kd;
#pragma unroll
            for (int a = 0; a < R_; a++) rr[a] += kd * wr_s[d*R_ + a];
        }
        float sclk = mval / fmaxf(fabsf(mval)*sqrtf(sk), 1e-12f);

        const size_t ebase = ((size_t)((b*H_ + h)*N_ + n))*R_;
        float es[R_], rs[R_], v1[R_];
#pragma unroll
        for (int a = 0; a < R_; a++){
            es[a] = e[a]*sclq;
            rs[a] = rr[a]*sclk;
            v1[a] = (es[a] + rs[a]) * lam2_s[a];
        }
        float* eo = out + ATTN_ELEMS + ebase;
        float* ro = out + ATTN_ELEMS + ESC_ELEMS + ebase;
#pragma unroll
        for (int a = 0; a < R_; a++){ eo[a] = es[a]; ro[a] = rs[a]; }

        float ev[R_];
#pragma unroll
        for (int u = 0; u < R_; u++) ev[u] = eps[ebase + u];
        float smp[R_];
#pragma unroll
        for (int s = 0; s < R_; s++){
            float am = 0.f;
#pragma unroll
            for (int a = 0; a < R_; a++) am += v1[a]*mu_s[a*R_ + s];
            smp[s] = am;
        }
#pragma unroll
        for (int a = 0; a < R_; a++)
#pragma unroll
            for (int u = 0; u < R_; u++){
                float f = v1[a]*ev[u];
#pragma unroll
                for (int c = 0; c < R_; c++)
                    smp[c] += f * S_s[(a*R_ + u)*R_ + c];
            }

        float* ob = out + ((size_t)(b*N_ + n))*C_ + h*D_;
#pragma unroll
        for (int d0 = 0; d0 < D_; d0 += 4){
            float4 o;
            float* op = (float*)&o;
#pragma unroll
            for (int dd = 0; dd < 4; dd++){
                float ao = fwb_s[d0 + dd];
#pragma unroll
                for (int a = 0; a < R_; a++) ao += smp[a]*fww_s[(d0 + dd)*R_ + a];
                op[dd] = ao;
            }
            *(float4*)(ob + d0) = o;
        }
    }
}

// ---------------------------------------------------------------------------
extern "C" void kernel_launch(void* const* d_in, const int* in_sizes, int n_in,
                              void* d_out, int out_size)
{
    const float* x         = (const float*)d_in[0];
    const float* mask      = (const float*)d_in[1];
    const float* eps       = (const float*)d_in[2];
    const float* qk_w      = (const float*)d_in[3];
    const float* we_p      = (const float*)d_in[4];
    const float* wr_p      = (const float*)d_in[5];
    const float* log_lam   = (const float*)d_in[6];
    const float* m_u       = (const float*)d_in[7];
    const float* s_tri     = (const float*)d_in[8];
    const float* log_ssqrt = (const float*)d_in[9];
    const float* fw_w      = (const float*)d_in[10];
    const float* fw_b      = (const float*)d_in[11];
    float* out = (float*)d_out;

    k_convert<<<4096, 256>>>(x, qk_w);
    k_setup_wewr<<<B_*H_, 64>>>(x, we_p, wr_p);
    k_setup_skl<<<1, 128>>>(log_lam, m_u, s_tri, log_ssqrt,
                            out + ATTN_ELEMS + 2*ESC_ELEMS);

    cudaFuncSetAttribute(k_main, cudaFuncAttributeMaxDynamicSharedMemorySize, SMEM_DYN);
    dim3 grid(N_/BM, H_, B_);
    k_main<<<grid, 256, SMEM_DYN>>>(mask, eps, log_lam, m_u, fw_w, fw_b, out);
}